// round 16
// baseline (speedup 1.0000x reference)
#include <cuda_runtime.h>
#include <cuda_bf16.h>
#include <mma.h>
#include <stdint.h>
#include <stddef.h>
#include <math.h>

using namespace nvcuda;

#define NNODES 12288
#define EDGES  196608
#define ETOT   (EDGES + NNODES)
#define DIN    3000
#define DH1    256
#define DH2    128
#define DLAT   16
#define DOUT   3000

#define Z_OFF   0
#define Z_LEN   (NNODES * DLAT)
#define Y_OFF   (Z_OFF + Z_LEN)
#define Y_LEN   (NNODES * DOUT)
#define MU_OFF  (Y_OFF + Y_LEN)
#define LS_OFF  (MU_OFF + Z_LEN)
#define ADJ_OFF (LS_OFF + Z_LEN)
#define NEG_INF (-3.402823466e38f)

#define KP_MAX 3008
#define A_ELEMS ((size_t)NNODES * KP_MAX)
#define W_ELEMS (3072 * 512)
#define CS_COLS 3072

__device__ __align__(16) float g_xlr[NNODES * 512];   // c1/c2 out, t2
__device__ __align__(16) float g_h  [NNODES * 256];   // h1/h2, t1
__device__ __align__(16) float g_cs [(size_t)NNODES * CS_COLS];  // padded GEMM scratch
__device__ __align__(16) __nv_bfloat16 g_ahi[A_ELEMS];
__device__ __align__(16) __nv_bfloat16 g_alo[A_ELEMS];
__device__ __align__(16) __nv_bfloat16 g_whi[W_ELEMS];
__device__ __align__(16) __nv_bfloat16 g_wlo[W_ELEMS];
__device__ float  g_e  [ETOT];
__device__ float  g_e2 [ETOT];
__device__ int    g_cnt[NNODES];
__device__ int    g_ptr[NNODES + 1];
__device__ int    g_cur[NNODES];
__device__ int    g_src[ETOT];
__device__ int    g_eid[ETOT];
__device__ double g_sum[512];
__device__ double g_sumsq[512];
__device__ float  g_scale[512];
__device__ float  g_shift[512];

__device__ __forceinline__ float fast_sigmoid(float v) {
    return 1.0f / (1.0f + __expf(-v));
}
__device__ __forceinline__ void edge_decode(const int* __restrict__ ei, int i, int& s, int& d) {
    if (i < EDGES) { s = ei[i]; d = ei[EDGES + i]; }
    else           { s = d = i - EDGES; }
}

// ---------------- bf16 split conversions ----------------
__global__ void convA_kernel(const float* __restrict__ A, int K, int Kp,
                             __nv_bfloat16* __restrict__ hi, __nv_bfloat16* __restrict__ lo) {
    size_t i = (size_t)blockIdx.x * blockDim.x + threadIdx.x;
    if (i >= (size_t)NNODES * Kp) return;
    int k = (int)(i % Kp);
    float v = (k < K) ? A[(i / Kp) * K + k] : 0.0f;
    __nv_bfloat16 h = __float2bfloat16(v);
    hi[i] = h;
    lo[i] = __float2bfloat16(v - __bfloat162float(h));
}
__global__ void zeroW_kernel(__nv_bfloat16* __restrict__ hi, __nv_bfloat16* __restrict__ lo, int total) {
    int i = blockIdx.x * blockDim.x + threadIdx.x;
    if (i >= total) return;
    hi[i] = __float2bfloat16(0.0f);
    lo[i] = __float2bfloat16(0.0f);
}
// W[K,N] -> rows [r0, r0+N) of Wt[Np x Kp]
__global__ void convW_kernel(const float* __restrict__ W, int K, int N, int Kp, int r0,
                             __nv_bfloat16* __restrict__ hi, __nv_bfloat16* __restrict__ lo) {
    int i = blockIdx.x * blockDim.x + threadIdx.x;
    if (i >= K * N) return;
    int k = i / N, n = i % N;
    float v = W[i];
    __nv_bfloat16 h = __float2bfloat16(v);
    size_t o = (size_t)(r0 + n) * Kp + k;
    hi[o] = h;
    lo[o] = __float2bfloat16(v - __bfloat162float(h));
}

// ---------------- WMMA bf16 GEMM (split hi/lo, cp.async double-buffered) ----
// C[M, ldc] = A[M,Kp] @ Wt[Np,Kp]^T. 128x128 tile, BK=32, 8 warps.
// EPI: 0 raw store; 1 sigmoid (staged, guarded); 2 bias+sigmoid (staged, guarded).
// Kp % 32 == 0, M % 128 == 0, Np % 128 == 0.
#define BKC  32
#define SPAD 40
#define BUF_ELEMS (128 * SPAD)
#define TCSM_BYTES (2 * 4 * BUF_ELEMS * 2)          // 81920 bytes
#define FPAD 132

#define CPA(dst, src) \
    asm volatile("cp.async.cg.shared.global [%0], [%1], 16;" :: "r"(dst), "l"(src))

template <int EPI>
__global__ __launch_bounds__(256)
void wmma_gemm_kernel(const __nv_bfloat16* __restrict__ Ahi, const __nv_bfloat16* __restrict__ Alo,
                      int Kp,
                      const __nv_bfloat16* __restrict__ Bhi, const __nv_bfloat16* __restrict__ Blo,
                      const float* __restrict__ bias,
                      float* __restrict__ C, int ldc, int Nact) {
    extern __shared__ __align__(16) __nv_bfloat16 sm[];
    const int tid = threadIdx.x;
    const int bm = blockIdx.y * 128, bn = blockIdx.x * 128;
    const int w  = tid >> 5;
    const int wr = (w >> 2) * 64;
    const int wc = (w & 3) * 32;
    const int NC = Kp / BKC;

    const int r_ = tid >> 1;
    const int q_ = (tid & 1) * 16;
    const uint32_t sbase = (uint32_t)__cvta_generic_to_shared(sm);
    const uint32_t so = (uint32_t)(r_ * SPAD + q_) * 2;
    const __nv_bfloat16* gAh = Ahi + (size_t)(bm + r_) * Kp + q_;
    const __nv_bfloat16* gAl = Alo + (size_t)(bm + r_) * Kp + q_;
    const __nv_bfloat16* gBh = Bhi + (size_t)(bn + r_) * Kp + q_;
    const __nv_bfloat16* gBl = Blo + (size_t)(bn + r_) * Kp + q_;

#define ISSUE(c, b) do { \
    uint32_t _ba = sbase + (uint32_t)(b) * (4 * BUF_ELEMS * 2); \
    size_t _ko = (size_t)(c) * BKC; \
    CPA(_ba + 0 * (BUF_ELEMS * 2) + so,      gAh + _ko); \
    CPA(_ba + 0 * (BUF_ELEMS * 2) + so + 16, gAh + _ko + 8); \
    CPA(_ba + 1 * (BUF_ELEMS * 2) + so,      gAl + _ko); \
    CPA(_ba + 1 * (BUF_ELEMS * 2) + so + 16, gAl + _ko + 8); \
    CPA(_ba + 2 * (BUF_ELEMS * 2) + so,      gBh + _ko); \
    CPA(_ba + 2 * (BUF_ELEMS * 2) + so + 16, gBh + _ko + 8); \
    CPA(_ba + 3 * (BUF_ELEMS * 2) + so,      gBl + _ko); \
    CPA(_ba + 3 * (BUF_ELEMS * 2) + so + 16, gBl + _ko + 8); \
    asm volatile("cp.async.commit_group;"); \
} while (0)

    wmma::fragment<wmma::accumulator, 16, 16, 16, float> acc[4][2];
#pragma unroll
    for (int i = 0; i < 4; ++i)
#pragma unroll
        for (int j = 0; j < 2; ++j) wmma::fill_fragment(acc[i][j], 0.0f);

    ISSUE(0, 0);
    for (int c = 0; c < NC; ++c) {
        const int b = c & 1;
        if (c + 1 < NC) {
            ISSUE(c + 1, (c + 1) & 1);
            asm volatile("cp.async.wait_group 1;");
        } else {
            asm volatile("cp.async.wait_group 0;");
        }
        __syncthreads();

        const __nv_bfloat16* sAh = sm + (size_t)b * 4 * BUF_ELEMS;
        const __nv_bfloat16* sAl = sAh + BUF_ELEMS;
        const __nv_bfloat16* sBh = sAh + 2 * BUF_ELEMS;
        const __nv_bfloat16* sBl = sAh + 3 * BUF_ELEMS;
#pragma unroll
        for (int kk = 0; kk < BKC; kk += 16) {
            wmma::fragment<wmma::matrix_a, 16, 16, 16, __nv_bfloat16, wmma::row_major> ah[4], al[4];
            wmma::fragment<wmma::matrix_b, 16, 16, 16, __nv_bfloat16, wmma::col_major> bh[2], bl[2];
#pragma unroll
            for (int i = 0; i < 4; ++i) {
                wmma::load_matrix_sync(ah[i], &sAh[(wr + i * 16) * SPAD + kk], SPAD);
                wmma::load_matrix_sync(al[i], &sAl[(wr + i * 16) * SPAD + kk], SPAD);
            }
#pragma unroll
            for (int j = 0; j < 2; ++j) {
                wmma::load_matrix_sync(bh[j], &sBh[(wc + j * 16) * SPAD + kk], SPAD);
                wmma::load_matrix_sync(bl[j], &sBl[(wc + j * 16) * SPAD + kk], SPAD);
            }
#pragma unroll
            for (int i = 0; i < 4; ++i)
#pragma unroll
                for (int j = 0; j < 2; ++j) {
                    wmma::mma_sync(acc[i][j], ah[i], bh[j], acc[i][j]);
                    wmma::mma_sync(acc[i][j], ah[i], bl[j], acc[i][j]);
                    wmma::mma_sync(acc[i][j], al[i], bh[j], acc[i][j]);
                }
        }
        __syncthreads();
    }

    if (EPI == 0) {
#pragma unroll
        for (int i = 0; i < 4; ++i)
#pragma unroll
            for (int j = 0; j < 2; ++j)
                wmma::store_matrix_sync(&C[(size_t)(bm + wr + i * 16) * ldc + bn + wc + j * 16],
                                        acc[i][j], ldc, wmma::mem_row_major);
    } else {
        // staged epilogue: frags -> smem -> guarded sigmoid writes
        float* sf = (float*)sm;                     // [128][FPAD], 67.6 KB < 80 KB
#pragma unroll
        for (int i = 0; i < 4; ++i)
#pragma unroll
            for (int j = 0; j < 2; ++j)
                wmma::store_matrix_sync(&sf[(wr + i * 16) * FPAD + wc + j * 16],
                                        acc[i][j], FPAD, wmma::mem_row_major);
        __syncthreads();
        for (int u4 = tid * 4; u4 < 128 * 128; u4 += 1024) {
            int row = u4 >> 7, col = u4 & 127;
            int gc = bn + col;
            float* dst = &C[(size_t)(bm + row) * ldc + gc];
            if (gc + 3 < Nact) {
                float4 v = *(float4*)&sf[row * FPAD + col];
                if (EPI == 2) {
                    v.x += bias[gc];     v.y += bias[gc + 1];
                    v.z += bias[gc + 2]; v.w += bias[gc + 3];
                }
                v.x = fast_sigmoid(v.x); v.y = fast_sigmoid(v.y);
                v.z = fast_sigmoid(v.z); v.w = fast_sigmoid(v.w);
                *(float4*)dst = v;
            } else {
#pragma unroll
                for (int e = 0; e < 4; ++e) {
                    if (gc + e < Nact) {
                        float v = sf[row * FPAD + col + e];
                        if (EPI == 2) v += bias[gc + e];
                        dst[e] = fast_sigmoid(v);
                    }
                }
            }
        }
    }
}

// ---------------- CSR build ----------------
__global__ void cnt_zero_kernel() {
    int i = blockIdx.x * blockDim.x + threadIdx.x;
    if (i < NNODES) g_cnt[i] = 0;
}
__global__ void hist_kernel(const int* __restrict__ ei) {
    int i = blockIdx.x * blockDim.x + threadIdx.x;
    if (i >= ETOT) return;
    int s, d; edge_decode(ei, i, s, d);
    atomicAdd(&g_cnt[d], 1);
}
__global__ void scan_kernel() {
    __shared__ int sh[1024];
    __shared__ int carry_sh;
    int tid = threadIdx.x;
    if (tid == 0) carry_sh = 0;
    __syncthreads();
    for (int c = 0; c < NNODES / 1024; ++c) {
        int idx = c * 1024 + tid;
        int v = g_cnt[idx];
        sh[tid] = v;
        __syncthreads();
        for (int off = 1; off < 1024; off <<= 1) {
            int t = (tid >= off) ? sh[tid - off] : 0;
            __syncthreads();
            sh[tid] += t;
            __syncthreads();
        }
        int incl = sh[tid], carry = carry_sh;
        g_ptr[idx] = carry + incl - v;
        g_cur[idx] = carry + incl - v;
        __syncthreads();
        if (tid == 1023) carry_sh = carry + incl;
        __syncthreads();
    }
    if (tid == 0) g_ptr[NNODES] = ETOT;
}
__global__ void scatter_kernel(const int* __restrict__ ei) {
    int i = blockIdx.x * blockDim.x + threadIdx.x;
    if (i >= ETOT) return;
    int s, d; edge_decode(ei, i, s, d);
    int pos = atomicAdd(&g_cur[d], 1);
    g_src[pos] = s;
    g_eid[pos] = i;
}

// ---------------- GATv2 edge machinery ----------------
__global__ void edge_score_kernel(const int* __restrict__ ei, const float* __restrict__ xl,
                                  const float* __restrict__ xr, const float* __restrict__ att,
                                  int D, int stride) {
    int w = (blockIdx.x * blockDim.x + threadIdx.x) >> 5;
    int lane = threadIdx.x & 31;
    if (w >= ETOT) return;
    int s, d; edge_decode(ei, w, s, d);
    float acc = 0.0f;
    for (int k = lane * 4; k < D; k += 128) {
        float4 l = *(const float4*)&xl[(size_t)s * stride + k];
        float4 r = *(const float4*)&xr[(size_t)d * stride + k];
        float4 a = *(const float4*)&att[k];
        float v;
        v = l.x + r.x; v = (v > 0.f) ? v : 0.2f * v; acc = fmaf(v, a.x, acc);
        v = l.y + r.y; v = (v > 0.f) ? v : 0.2f * v; acc = fmaf(v, a.y, acc);
        v = l.z + r.z; v = (v > 0.f) ? v : 0.2f * v; acc = fmaf(v, a.z, acc);
        v = l.w + r.w; v = (v > 0.f) ? v : 0.2f * v; acc = fmaf(v, a.w, acc);
    }
#pragma unroll
    for (int o = 16; o; o >>= 1) acc += __shfl_xor_sync(0xffffffffu, acc, o);
    if (lane == 0) g_e[w] = acc;
}

template <int D, int RELU>
__global__ void node_agg_kernel(const float* __restrict__ xl, int stride,
                                const float* __restrict__ bias, float* __restrict__ out) {
    int node = (blockIdx.x * blockDim.x + threadIdx.x) >> 5;
    int lane = threadIdx.x & 31;
    if (node >= NNODES) return;
    int p0 = g_ptr[node], p1 = g_ptr[node + 1];
    float m = NEG_INF;
    for (int j = p0 + lane; j < p1; j += 32) m = fmaxf(m, g_e[g_eid[j]]);
#pragma unroll
    for (int o = 16; o; o >>= 1) m = fmaxf(m, __shfl_xor_sync(0xffffffffu, m, o));
    float ssum = 0.0f;
    for (int j = p0 + lane; j < p1; j += 32) ssum += __expf(g_e[g_eid[j]] - m);
#pragma unroll
    for (int o = 16; o; o >>= 1) ssum += __shfl_xor_sync(0xffffffffu, ssum, o);
    float inv = 1.0f / ssum;
    constexpr int NR = D / 128;
    float4 acc[NR];
#pragma unroll
    for (int r = 0; r < NR; ++r) acc[r] = make_float4(0.f, 0.f, 0.f, 0.f);
    for (int j = p0; j < p1; ++j) {
        int src = g_src[j];
        float alpha = __expf(g_e[g_eid[j]] - m) * inv;
        const float4* row = (const float4*)(xl + (size_t)src * stride);
#pragma unroll
        for (int r = 0; r < NR; ++r) {
            float4 v = row[lane + 32 * r];
            acc[r].x = fmaf(alpha, v.x, acc[r].x);
            acc[r].y = fmaf(alpha, v.y, acc[r].y);
            acc[r].z = fmaf(alpha, v.z, acc[r].z);
            acc[r].w = fmaf(alpha, v.w, acc[r].w);
        }
    }
#pragma unroll
    for (int r = 0; r < NR; ++r) {
        int col = 4 * (lane + 32 * r);
        float4 b = *(const float4*)&bias[col];
        float4 o;
        o.x = acc[r].x + b.x; o.y = acc[r].y + b.y;
        o.z = acc[r].z + b.z; o.w = acc[r].w + b.w;
        if (RELU) {
            o.x = fmaxf(o.x, 0.f); o.y = fmaxf(o.y, 0.f);
            o.z = fmaxf(o.z, 0.f); o.w = fmaxf(o.w, 0.f);
        }
        *(float4*)&out[(size_t)node * D + col] = o;
    }
}

// heads: hcat row layout (stride S): [xl_mu(16)|xr_mu(16)|xl_ls(16)|xr_ls(16)|pad]
__global__ void edge_score_heads_kernel(const int* __restrict__ ei, const float* __restrict__ hcat,
                                        int S,
                                        const float* __restrict__ att_mu, const float* __restrict__ att_ls) {
    int i = blockIdx.x * blockDim.x + threadIdx.x;
    if (i >= ETOT) return;
    int s, d; edge_decode(ei, i, s, d);
    const float4* Sp = (const float4*)(hcat + (size_t)s * S);
    const float4* Dp = (const float4*)(hcat + (size_t)d * S);
    const float4* Am = (const float4*)att_mu;
    const float4* Al = (const float4*)att_ls;
    float emu = 0.f, els = 0.f;
#pragma unroll
    for (int q = 0; q < 4; ++q) {
        float4 l = Sp[q], r = Dp[4 + q], a = Am[q];
        float v;
        v = l.x + r.x; v = (v > 0.f) ? v : 0.2f * v; emu = fmaf(v, a.x, emu);
        v = l.y + r.y; v = (v > 0.f) ? v : 0.2f * v; emu = fmaf(v, a.y, emu);
        v = l.z + r.z; v = (v > 0.f) ? v : 0.2f * v; emu = fmaf(v, a.z, emu);
        v = l.w + r.w; v = (v > 0.f) ? v : 0.2f * v; emu = fmaf(v, a.w, emu);
        float4 l2 = Sp[8 + q], r2 = Dp[12 + q], a2 = Al[q];
        v = l2.x + r2.x; v = (v > 0.f) ? v : 0.2f * v; els = fmaf(v, a2.x, els);
        v = l2.y + r2.y; v = (v > 0.f) ? v : 0.2f * v; els = fmaf(v, a2.y, els);
        v = l2.z + r2.z; v = (v > 0.f) ? v : 0.2f * v; els = fmaf(v, a2.z, els);
        v = l2.w + r2.w; v = (v > 0.f) ? v : 0.2f * v; els = fmaf(v, a2.w, els);
    }
    g_e[i] = emu;
    g_e2[i] = els;
}

__global__ void node_agg_heads_kernel(const float* __restrict__ hcat, int S,
                                      const float* __restrict__ bmu, const float* __restrict__ bls,
                                      float* __restrict__ omu, float* __restrict__ ols) {
    int node = (blockIdx.x * blockDim.x + threadIdx.x) >> 5;
    int lane = threadIdx.x & 31;
    if (node >= NNODES) return;
    int p0 = g_ptr[node], p1 = g_ptr[node + 1];
    float mmu = NEG_INF, mls = NEG_INF;
    for (int j = p0 + lane; j < p1; j += 32) {
        int e = g_eid[j];
        mmu = fmaxf(mmu, g_e[e]);
        mls = fmaxf(mls, g_e2[e]);
    }
#pragma unroll
    for (int o = 16; o; o >>= 1) {
        mmu = fmaxf(mmu, __shfl_xor_sync(0xffffffffu, mmu, o));
        mls = fmaxf(mls, __shfl_xor_sync(0xffffffffu, mls, o));
    }
    float smu = 0.f, sls = 0.f;
    for (int j = p0 + lane; j < p1; j += 32) {
        int e = g_eid[j];
        smu += __expf(g_e[e] - mmu);
        sls += __expf(g_e2[e] - mls);
    }
#pragma unroll
    for (int o = 16; o; o >>= 1) {
        smu += __shfl_xor_sync(0xffffffffu, smu, o);
        sls += __shfl_xor_sync(0xffffffffu, sls, o);
    }
    float imu = 1.0f / smu, ils = 1.0f / sls;
    float acc = 0.0f;
    for (int j = p0; j < p1; ++j) {
        int s = g_src[j], e = g_eid[j];
        const float* row = hcat + (size_t)s * S;
        if (lane < 16) acc = fmaf(__expf(g_e[e]  - mmu) * imu, row[lane],      acc);
        else           acc = fmaf(__expf(g_e2[e] - mls) * ils, row[16 + lane], acc);
    }
    if (lane < 16) omu[(size_t)node * 16 + lane]        = acc + bmu[lane];
    else           ols[(size_t)node * 16 + (lane - 16)] = acc + bls[lane - 16];
}

__global__ void z_kernel(const float* __restrict__ eps, const float* __restrict__ ls,
                         const float* __restrict__ mu, float* __restrict__ z, int total) {
    int i = blockIdx.x * blockDim.x + threadIdx.x;
    if (i < total) z[i] = eps[i] * expf(ls[i]) + mu[i];
}

// ---------------- BatchNorm ----------------
__global__ void bn_zero_kernel(int F) {
    int i = blockIdx.x * blockDim.x + threadIdx.x;
    if (i < F) { g_sum[i] = 0.0; g_sumsq[i] = 0.0; }
}
__global__ void bn_stats_kernel(const float* __restrict__ x, int rows, int F) {
    int chunk = (rows + gridDim.x - 1) / gridDim.x;
    int r0 = blockIdx.x * chunk, r1 = min(rows, r0 + chunk), t = threadIdx.x;
    if (F <= 256) {
        int per = 256 / F, f = t % F, roff = t / F;
        double s = 0.0, q = 0.0;
        for (int r = r0 + roff; r < r1; r += per) {
            float v = x[(size_t)r * F + f];
            s += v; q += (double)v * v;
        }
        atomicAdd(&g_sum[f], s); atomicAdd(&g_sumsq[f], q);
    } else {
        for (int f = t; f < F; f += 256) {
            double s = 0.0, q = 0.0;
            for (int r = r0; r < r1; ++r) {
                float v = x[(size_t)r * F + f];
                s += v; q += (double)v * v;
            }
            atomicAdd(&g_sum[f], s); atomicAdd(&g_sumsq[f], q);
        }
    }
}
__global__ void bn_finalize_kernel(const float* __restrict__ g, const float* __restrict__ b,
                                   int F, int rows) {
    int f = blockIdx.x * blockDim.x + threadIdx.x;
    if (f >= F) return;
    double mean = g_sum[f] / (double)rows;
    double var  = g_sumsq[f] / (double)rows - mean * mean;
    double inv  = rsqrt(var + 1e-5);
    float sc = (float)((double)g[f] * inv);
    g_scale[f] = sc;
    g_shift[f] = b[f] - (float)mean * sc;
}
__global__ void bn_apply_kernel(float* __restrict__ x, int total, int F) {
    int i = blockIdx.x * blockDim.x + threadIdx.x;
    if (i >= total) return;
    int f = i % F;
    float v = x[i] * g_scale[f] + g_shift[f];
    x[i] = (v > 0.0f) ? v : 0.2f * v;
}

// ---------------- Host helpers ----------------
static void conv_A(const float* A, int K, int Kp, __nv_bfloat16* hi, __nv_bfloat16* lo) {
    size_t total = (size_t)NNODES * Kp;
    convA_kernel<<<(unsigned)((total + 255) / 256), 256>>>(A, K, Kp, hi, lo);
}
static void wmma_gemm(const __nv_bfloat16* ahi, const __nv_bfloat16* alo, int Kp,
                      const __nv_bfloat16* whi, const __nv_bfloat16* wlo,
                      const float* bias, float* C, int Np, int ldc, int Nact, int epi) {
    dim3 grid(Np / 128, NNODES / 128);
    if (epi == 0)
        wmma_gemm_kernel<0><<<grid, 256, TCSM_BYTES>>>(ahi, alo, Kp, whi, wlo, bias, C, ldc, Nact);
    else if (epi == 1)
        wmma_gemm_kernel<1><<<grid, 256, TCSM_BYTES>>>(ahi, alo, Kp, whi, wlo, bias, C, ldc, Nact);
    else
        wmma_gemm_kernel<2><<<grid, 256, TCSM_BYTES>>>(ahi, alo, Kp, whi, wlo, bias, C, ldc, Nact);
}
static void run_bn(float* x, const float* g, const float* b, int rows, int F) {
    bn_zero_kernel<<<(F + 255) / 256, 256>>>(F);
    bn_stats_kernel<<<64, 256>>>(x, rows, F);
    bn_finalize_kernel<<<(F + 255) / 256, 256>>>(g, b, F, rows);
    bn_apply_kernel<<<(rows * F + 255) / 256, 256>>>(x, rows * F, F);
}

// ---------------- kernel_launch ----------------
extern "C" void kernel_launch(void* const* d_in, const int* in_sizes, int n_in,
                              void* d_out, int out_size) {
    (void)in_sizes; (void)n_in; (void)out_size;

    const float* x       = (const float*)d_in[0];
    const int*   ei      = (const int*)  d_in[1];
    const float* eps     = (const float*)d_in[2];
    const float* c1_Wl   = (const float*)d_in[3];
    const float* c1_Wr   = (const float*)d_in[4];
    const float* c1_att  = (const float*)d_in[5];
    const float* c1_b    = (const float*)d_in[6];
    const float* c2_Wl   = (const float*)d_in[7];
    const float* c2_Wr   = (const float*)d_in[8];
    const float* c2_att  = (const float*)d_in[9];
    const float* c2_b    = (const float*)d_in[10];
    const float* cmu_Wl  = (const float*)d_in[11];
    const float* cmu_Wr  = (const float*)d_in[12];
    const float* cmu_att = (const float*)d_in[13];
    const float* cmu_b   = (const float*)d_in[14];
    const float* cls_Wl  = (const float*)d_in[15];
    const float* cls_Wr  = (const float*)d_in[16];
    const float* cls_att = (const float*)d_in[17];
    const float* cls_b   = (const float*)d_in[18];
    const float* d1_W    = (const float*)d_in[19];
    const float* bn1_g   = (const float*)d_in[21];
    const float* bn1_b   = (const float*)d_in[22];
    const float* d2_W    = (const float*)d_in[23];
    const float* bn2_g   = (const float*)d_in[25];
    const float* bn2_b   = (const float*)d_in[26];
    const float* d3_W    = (const float*)d_in[27];
    const float* d3_b    = (const float*)d_in[28];

    float* out   = (float*)d_out;
    float* d_z   = out + Z_OFF;
    float* d_y   = out + Y_OFF;
    float* d_mu  = out + MU_OFF;
    float* d_ls  = out + LS_OFF;
    float* d_adj = out + ADJ_OFF;

    cudaFuncSetAttribute(wmma_gemm_kernel<0>, cudaFuncAttributeMaxDynamicSharedMemorySize, TCSM_BYTES);
    cudaFuncSetAttribute(wmma_gemm_kernel<1>, cudaFuncAttributeMaxDynamicSharedMemorySize, TCSM_BYTES);
    cudaFuncSetAttribute(wmma_gemm_kernel<2>, cudaFuncAttributeMaxDynamicSharedMemorySize, TCSM_BYTES);

    float *xlr, *h, *cs;
    __nv_bfloat16 *ahi, *alo, *whi, *wlo;
    cudaGetSymbolAddress((void**)&xlr, g_xlr);
    cudaGetSymbolAddress((void**)&h,   g_h);
    cudaGetSymbolAddress((void**)&cs,  g_cs);
    cudaGetSymbolAddress((void**)&ahi, g_ahi);
    cudaGetSymbolAddress((void**)&alo, g_alo);
    cudaGetSymbolAddress((void**)&whi, g_whi);
    cudaGetSymbolAddress((void**)&wlo, g_wlo);

    const int EB = (ETOT + 255) / 256;
    const int EW = ETOT / 8;
    const int NW = NNODES / 8;

    cnt_zero_kernel<<<(NNODES + 255) / 256, 256>>>();
    hist_kernel<<<EB, 256>>>(ei);
    scan_kernel<<<1, 1024>>>();
    scatter_kernel<<<EB, 256>>>(ei);

    // GAT layer 1: 3000 -> 256 (fused Wl|Wr, Np=512, Kp=3008)
    zeroW_kernel<<<(512 * 3008 + 255) / 256, 256>>>(whi, wlo, 512 * 3008);
    convW_kernel<<<(DIN * 256 + 255) / 256, 256>>>(c1_Wl, DIN, 256, 3008, 0,   whi, wlo);
    convW_kernel<<<(DIN * 256 + 255) / 256, 256>>>(c1_Wr, DIN, 256, 3008, 256, whi, wlo);
    conv_A(x, DIN, 3008, ahi, alo);
    wmma_gemm(ahi, alo, 3008, whi, wlo, nullptr, xlr, 512, 512, 512, 0);
    edge_score_kernel<<<EW, 256>>>(ei, xlr, xlr + DH1, c1_att, DH1, 512);
    node_agg_kernel<DH1, 1><<<NW, 256>>>(xlr, 512, c1_b, h);

    // GAT layer 2: 256 -> 128 (Np=256)
    zeroW_kernel<<<(256 * 256 + 255) / 256, 256>>>(whi, wlo, 256 * 256);
    convW_kernel<<<(256 * 128 + 255) / 256, 256>>>(c2_Wl, 256, 128, 256, 0,   whi, wlo);
    convW_kernel<<<(256 * 128 + 255) / 256, 256>>>(c2_Wr, 256, 128, 256, 128, whi, wlo);
    conv_A(h, 256, 256, ahi, alo);
    wmma_gemm(ahi, alo, 256, whi, wlo, nullptr, xlr, 256, 256, 256, 0);
    edge_score_kernel<<<EW, 256>>>(ei, xlr, xlr + DH2, c2_att, DH2, 256);
    node_agg_kernel<DH2, 1><<<NW, 256>>>(xlr, 256, c2_b, h);

    // mu/logstd heads: 128 -> 4x16 (Np=128) -> cs stride 128
    zeroW_kernel<<<(128 * 128 + 255) / 256, 256>>>(whi, wlo, 128 * 128);
    convW_kernel<<<(128 * 16 + 255) / 256, 256>>>(cmu_Wl, 128, 16, 128, 0,  whi, wlo);
    convW_kernel<<<(128 * 16 + 255) / 256, 256>>>(cmu_Wr, 128, 16, 128, 16, whi, wlo);
    convW_kernel<<<(128 * 16 + 255) / 256, 256>>>(cls_Wl, 128, 16, 128, 32, whi, wlo);
    convW_kernel<<<(128 * 16 + 255) / 256, 256>>>(cls_Wr, 128, 16, 128, 48, whi, wlo);
    conv_A(h, 128, 128, ahi, alo);
    wmma_gemm(ahi, alo, 128, whi, wlo, nullptr, cs, 128, 128, 128, 0);
    edge_score_heads_kernel<<<EB, 256>>>(ei, cs, 128, cmu_att, cls_att);
    node_agg_heads_kernel<<<NW, 256>>>(cs, 128, cmu_b, cls_b, d_mu, d_ls);

    // z, then single z->bf16 split (Kp=32) shared by adj and d1
    z_kernel<<<(Z_LEN + 255) / 256, 256>>>(eps, d_ls, d_mu, d_z, Z_LEN);
    conv_A(d_z, 16, 32, ahi, alo);

    // adj = sigmoid(z z^T) on tensor cores: A = B = z-split, EPI=1 (sigmoid)
    wmma_gemm(ahi, alo, 32, ahi, alo, nullptr, d_adj, NNODES, NNODES, NNODES, 1);

    // d1: 16 -> 128 (bias cancels in train-mode BN), Kp=32 -> g_h
    zeroW_kernel<<<(128 * 32 + 255) / 256, 256>>>(whi, wlo, 128 * 32);
    convW_kernel<<<(16 * 128 + 255) / 256, 256>>>(d1_W, 16, 128, 32, 0, whi, wlo);
    wmma_gemm(ahi, alo, 32, whi, wlo, nullptr, h, 128, 128, 128, 0);
    run_bn(h, bn1_g, bn1_b, NNODES, 128);

    // d2: 128 -> 512 (bias cancels in BN) -> g_xlr
    zeroW_kernel<<<(512 * 128 + 255) / 256, 256>>>(whi, wlo, 512 * 128);
    convW_kernel<<<(128 * 512 + 255) / 256, 256>>>(d2_W, 128, 512, 128, 0, whi, wlo);
    conv_A(h, 128, 128, ahi, alo);
    wmma_gemm(ahi, alo, 128, whi, wlo, nullptr, xlr, 512, 512, 512, 0);
    run_bn(xlr, bn2_g, bn2_b, NNODES, 512);

    // d3: 512 -> 3000, EPI=2 (bias+sigmoid) direct to d_y (ldc=3000, guarded)
    zeroW_kernel<<<(3072 * 512 + 255) / 256, 256>>>(whi, wlo, 3072 * 512);
    convW_kernel<<<(512 * DOUT + 255) / 256, 256>>>(d3_W, 512, DOUT, 512, 0, whi, wlo);
    conv_A(xlr, 512, 512, ahi, alo);
    wmma_gemm(ahi, alo, 512, whi, wlo, d3_b, d_y, 3072, DOUT, DOUT, 2);
}

// round 17
// speedup vs baseline: 1.1214x; 1.1214x over previous
#include <cuda_runtime.h>
#include <cuda_bf16.h>
#include <mma.h>
#include <stdint.h>
#include <stddef.h>
#include <math.h>

using namespace nvcuda;

#define NNODES 12288
#define EDGES  196608
#define ETOT   (EDGES + NNODES)
#define DIN    3000
#define DH1    256
#define DH2    128
#define DLAT   16
#define DOUT   3000

#define Z_OFF   0
#define Z_LEN   (NNODES * DLAT)
#define Y_OFF   (Z_OFF + Z_LEN)
#define Y_LEN   (NNODES * DOUT)
#define MU_OFF  (Y_OFF + Y_LEN)
#define LS_OFF  (MU_OFF + Z_LEN)
#define ADJ_OFF (LS_OFF + Z_LEN)
#define NEG_INF (-3.402823466e38f)

#define KP_MAX 3008
#define A_ELEMS ((size_t)NNODES * KP_MAX)
#define W_ELEMS (3072 * 512)
#define CS_COLS 3072

__device__ __align__(16) float g_xlr[NNODES * 512];   // c1/c2 out, t2
__device__ __align__(16) float g_h  [NNODES * 256];   // h1/h2, t1
__device__ __align__(16) float g_cs [(size_t)NNODES * CS_COLS];  // padded GEMM scratch
__device__ __align__(16) __nv_bfloat16 g_ahi[A_ELEMS];
__device__ __align__(16) __nv_bfloat16 g_alo[A_ELEMS];
__device__ __align__(16) __nv_bfloat16 g_whi[W_ELEMS];
__device__ __align__(16) __nv_bfloat16 g_wlo[W_ELEMS];
__device__ float  g_e  [ETOT];
__device__ float  g_e2 [ETOT];
__device__ int    g_cnt[NNODES];
__device__ int    g_ptr[NNODES + 1];
__device__ int    g_cur[NNODES];
__device__ int    g_src[ETOT];
__device__ int    g_eid[ETOT];
__device__ double g_sum[512];
__device__ double g_sumsq[512];
__device__ float  g_scale[512];
__device__ float  g_shift[512];

__device__ __forceinline__ float fast_sigmoid(float v) {
    return 1.0f / (1.0f + __expf(-v));
}
__device__ __forceinline__ void edge_decode(const int* __restrict__ ei, int i, int& s, int& d) {
    if (i < EDGES) { s = ei[i]; d = ei[EDGES + i]; }
    else           { s = d = i - EDGES; }
}

// ---------------- bf16 split conversions ----------------
__global__ void convA_kernel(const float* __restrict__ A, int K, int Kp,
                             __nv_bfloat16* __restrict__ hi, __nv_bfloat16* __restrict__ lo) {
    size_t i = (size_t)blockIdx.x * blockDim.x + threadIdx.x;
    if (i >= (size_t)NNODES * Kp) return;
    int k = (int)(i % Kp);
    float v = (k < K) ? A[(i / Kp) * K + k] : 0.0f;
    __nv_bfloat16 h = __float2bfloat16(v);
    hi[i] = h;
    lo[i] = __float2bfloat16(v - __bfloat162float(h));
}
__global__ void zeroW_kernel(__nv_bfloat16* __restrict__ hi, __nv_bfloat16* __restrict__ lo, int total) {
    int i = blockIdx.x * blockDim.x + threadIdx.x;
    if (i >= total) return;
    hi[i] = __float2bfloat16(0.0f);
    lo[i] = __float2bfloat16(0.0f);
}
// W[K,N] -> rows [r0, r0+N) of Wt[Np x Kp]
__global__ void convW_kernel(const float* __restrict__ W, int K, int N, int Kp, int r0,
                             __nv_bfloat16* __restrict__ hi, __nv_bfloat16* __restrict__ lo) {
    int i = blockIdx.x * blockDim.x + threadIdx.x;
    if (i >= K * N) return;
    int k = i / N, n = i % N;
    float v = W[i];
    __nv_bfloat16 h = __float2bfloat16(v);
    size_t o = (size_t)(r0 + n) * Kp + k;
    hi[o] = h;
    lo[o] = __float2bfloat16(v - __bfloat162float(h));
}

// ---------------- WMMA bf16 GEMM (split hi/lo, cp.async double-buffered) ----
// C[M, ldc] = A[M,Kp] @ Wt[Np,Kp]^T. 128x128 tile, BK=32, 8 warps.
// EPI: 0 raw store; 2 bias+sigmoid (staged, guarded, direct to output).
// Kp % 32 == 0, M % 128 == 0, Np % 128 == 0.
#define BKC  32
#define SPAD 40
#define BUF_ELEMS (128 * SPAD)
#define TCSM_BYTES (2 * 4 * BUF_ELEMS * 2)          // 81920 bytes
#define FPAD 132

#define CPA(dst, src) \
    asm volatile("cp.async.cg.shared.global [%0], [%1], 16;" :: "r"(dst), "l"(src))

template <int EPI>
__global__ __launch_bounds__(256)
void wmma_gemm_kernel(const __nv_bfloat16* __restrict__ Ahi, const __nv_bfloat16* __restrict__ Alo,
                      int Kp,
                      const __nv_bfloat16* __restrict__ Bhi, const __nv_bfloat16* __restrict__ Blo,
                      const float* __restrict__ bias,
                      float* __restrict__ C, int ldc, int Nact) {
    extern __shared__ __align__(16) __nv_bfloat16 sm[];
    const int tid = threadIdx.x;
    const int bm = blockIdx.y * 128, bn = blockIdx.x * 128;
    const int w  = tid >> 5;
    const int wr = (w >> 2) * 64;
    const int wc = (w & 3) * 32;
    const int NC = Kp / BKC;

    const int r_ = tid >> 1;
    const int q_ = (tid & 1) * 16;
    const uint32_t sbase = (uint32_t)__cvta_generic_to_shared(sm);
    const uint32_t so = (uint32_t)(r_ * SPAD + q_) * 2;
    const __nv_bfloat16* gAh = Ahi + (size_t)(bm + r_) * Kp + q_;
    const __nv_bfloat16* gAl = Alo + (size_t)(bm + r_) * Kp + q_;
    const __nv_bfloat16* gBh = Bhi + (size_t)(bn + r_) * Kp + q_;
    const __nv_bfloat16* gBl = Blo + (size_t)(bn + r_) * Kp + q_;

#define ISSUE(c, b) do { \
    uint32_t _ba = sbase + (uint32_t)(b) * (4 * BUF_ELEMS * 2); \
    size_t _ko = (size_t)(c) * BKC; \
    CPA(_ba + 0 * (BUF_ELEMS * 2) + so,      gAh + _ko); \
    CPA(_ba + 0 * (BUF_ELEMS * 2) + so + 16, gAh + _ko + 8); \
    CPA(_ba + 1 * (BUF_ELEMS * 2) + so,      gAl + _ko); \
    CPA(_ba + 1 * (BUF_ELEMS * 2) + so + 16, gAl + _ko + 8); \
    CPA(_ba + 2 * (BUF_ELEMS * 2) + so,      gBh + _ko); \
    CPA(_ba + 2 * (BUF_ELEMS * 2) + so + 16, gBh + _ko + 8); \
    CPA(_ba + 3 * (BUF_ELEMS * 2) + so,      gBl + _ko); \
    CPA(_ba + 3 * (BUF_ELEMS * 2) + so + 16, gBl + _ko + 8); \
    asm volatile("cp.async.commit_group;"); \
} while (0)

    wmma::fragment<wmma::accumulator, 16, 16, 16, float> acc[4][2];
#pragma unroll
    for (int i = 0; i < 4; ++i)
#pragma unroll
        for (int j = 0; j < 2; ++j) wmma::fill_fragment(acc[i][j], 0.0f);

    ISSUE(0, 0);
    for (int c = 0; c < NC; ++c) {
        const int b = c & 1;
        if (c + 1 < NC) {
            ISSUE(c + 1, (c + 1) & 1);
            asm volatile("cp.async.wait_group 1;");
        } else {
            asm volatile("cp.async.wait_group 0;");
        }
        __syncthreads();

        const __nv_bfloat16* sAh = sm + (size_t)b * 4 * BUF_ELEMS;
        const __nv_bfloat16* sAl = sAh + BUF_ELEMS;
        const __nv_bfloat16* sBh = sAh + 2 * BUF_ELEMS;
        const __nv_bfloat16* sBl = sAh + 3 * BUF_ELEMS;
#pragma unroll
        for (int kk = 0; kk < BKC; kk += 16) {
            wmma::fragment<wmma::matrix_a, 16, 16, 16, __nv_bfloat16, wmma::row_major> ah[4], al[4];
            wmma::fragment<wmma::matrix_b, 16, 16, 16, __nv_bfloat16, wmma::col_major> bh[2], bl[2];
#pragma unroll
            for (int i = 0; i < 4; ++i) {
                wmma::load_matrix_sync(ah[i], &sAh[(wr + i * 16) * SPAD + kk], SPAD);
                wmma::load_matrix_sync(al[i], &sAl[(wr + i * 16) * SPAD + kk], SPAD);
            }
#pragma unroll
            for (int j = 0; j < 2; ++j) {
                wmma::load_matrix_sync(bh[j], &sBh[(wc + j * 16) * SPAD + kk], SPAD);
                wmma::load_matrix_sync(bl[j], &sBl[(wc + j * 16) * SPAD + kk], SPAD);
            }
#pragma unroll
            for (int i = 0; i < 4; ++i)
#pragma unroll
                for (int j = 0; j < 2; ++j) {
                    wmma::mma_sync(acc[i][j], ah[i], bh[j], acc[i][j]);
                    wmma::mma_sync(acc[i][j], ah[i], bl[j], acc[i][j]);
                    wmma::mma_sync(acc[i][j], al[i], bh[j], acc[i][j]);
                }
        }
        __syncthreads();
    }

    if (EPI == 0) {
#pragma unroll
        for (int i = 0; i < 4; ++i)
#pragma unroll
            for (int j = 0; j < 2; ++j)
                wmma::store_matrix_sync(&C[(size_t)(bm + wr + i * 16) * ldc + bn + wc + j * 16],
                                        acc[i][j], ldc, wmma::mem_row_major);
    } else {
        // staged epilogue: frags -> smem -> guarded bias+sigmoid writes
        float* sf = (float*)sm;                     // [128][FPAD], 67.6 KB < 80 KB
#pragma unroll
        for (int i = 0; i < 4; ++i)
#pragma unroll
            for (int j = 0; j < 2; ++j)
                wmma::store_matrix_sync(&sf[(wr + i * 16) * FPAD + wc + j * 16],
                                        acc[i][j], FPAD, wmma::mem_row_major);
        __syncthreads();
        for (int u4 = tid * 4; u4 < 128 * 128; u4 += 1024) {
            int row = u4 >> 7, col = u4 & 127;
            int gc = bn + col;
            float* dst = &C[(size_t)(bm + row) * ldc + gc];
            if (gc + 3 < Nact) {
                float4 v = *(float4*)&sf[row * FPAD + col];
                v.x += bias[gc];     v.y += bias[gc + 1];
                v.z += bias[gc + 2]; v.w += bias[gc + 3];
                v.x = fast_sigmoid(v.x); v.y = fast_sigmoid(v.y);
                v.z = fast_sigmoid(v.z); v.w = fast_sigmoid(v.w);
                *(float4*)dst = v;
            } else {
#pragma unroll
                for (int e = 0; e < 4; ++e) {
                    if (gc + e < Nact) {
                        float v = sf[row * FPAD + col + e] + bias[gc + e];
                        dst[e] = fast_sigmoid(v);
                    }
                }
            }
        }
    }
}

// ---------------- CSR build ----------------
__global__ void cnt_zero_kernel() {
    int i = blockIdx.x * blockDim.x + threadIdx.x;
    if (i < NNODES) g_cnt[i] = 0;
}
__global__ void hist_kernel(const int* __restrict__ ei) {
    int i = blockIdx.x * blockDim.x + threadIdx.x;
    if (i >= ETOT) return;
    int s, d; edge_decode(ei, i, s, d);
    atomicAdd(&g_cnt[d], 1);
}
__global__ void scan_kernel() {
    __shared__ int sh[1024];
    __shared__ int carry_sh;
    int tid = threadIdx.x;
    if (tid == 0) carry_sh = 0;
    __syncthreads();
    for (int c = 0; c < NNODES / 1024; ++c) {
        int idx = c * 1024 + tid;
        int v = g_cnt[idx];
        sh[tid] = v;
        __syncthreads();
        for (int off = 1; off < 1024; off <<= 1) {
            int t = (tid >= off) ? sh[tid - off] : 0;
            __syncthreads();
            sh[tid] += t;
            __syncthreads();
        }
        int incl = sh[tid], carry = carry_sh;
        g_ptr[idx] = carry + incl - v;
        g_cur[idx] = carry + incl - v;
        __syncthreads();
        if (tid == 1023) carry_sh = carry + incl;
        __syncthreads();
    }
    if (tid == 0) g_ptr[NNODES] = ETOT;
}
__global__ void scatter_kernel(const int* __restrict__ ei) {
    int i = blockIdx.x * blockDim.x + threadIdx.x;
    if (i >= ETOT) return;
    int s, d; edge_decode(ei, i, s, d);
    int pos = atomicAdd(&g_cur[d], 1);
    g_src[pos] = s;
    g_eid[pos] = i;
}

// ---------------- GATv2 edge machinery ----------------
__global__ void edge_score_kernel(const int* __restrict__ ei, const float* __restrict__ xl,
                                  const float* __restrict__ xr, const float* __restrict__ att,
                                  int D, int stride) {
    int w = (blockIdx.x * blockDim.x + threadIdx.x) >> 5;
    int lane = threadIdx.x & 31;
    if (w >= ETOT) return;
    int s, d; edge_decode(ei, w, s, d);
    float acc = 0.0f;
    for (int k = lane * 4; k < D; k += 128) {
        float4 l = *(const float4*)&xl[(size_t)s * stride + k];
        float4 r = *(const float4*)&xr[(size_t)d * stride + k];
        float4 a = *(const float4*)&att[k];
        float v;
        v = l.x + r.x; v = (v > 0.f) ? v : 0.2f * v; acc = fmaf(v, a.x, acc);
        v = l.y + r.y; v = (v > 0.f) ? v : 0.2f * v; acc = fmaf(v, a.y, acc);
        v = l.z + r.z; v = (v > 0.f) ? v : 0.2f * v; acc = fmaf(v, a.z, acc);
        v = l.w + r.w; v = (v > 0.f) ? v : 0.2f * v; acc = fmaf(v, a.w, acc);
    }
#pragma unroll
    for (int o = 16; o; o >>= 1) acc += __shfl_xor_sync(0xffffffffu, acc, o);
    if (lane == 0) g_e[w] = acc;
}

template <int D, int RELU>
__global__ void node_agg_kernel(const float* __restrict__ xl, int stride,
                                const float* __restrict__ bias, float* __restrict__ out) {
    int node = (blockIdx.x * blockDim.x + threadIdx.x) >> 5;
    int lane = threadIdx.x & 31;
    if (node >= NNODES) return;
    int p0 = g_ptr[node], p1 = g_ptr[node + 1];
    float m = NEG_INF;
    for (int j = p0 + lane; j < p1; j += 32) m = fmaxf(m, g_e[g_eid[j]]);
#pragma unroll
    for (int o = 16; o; o >>= 1) m = fmaxf(m, __shfl_xor_sync(0xffffffffu, m, o));
    float ssum = 0.0f;
    for (int j = p0 + lane; j < p1; j += 32) ssum += __expf(g_e[g_eid[j]] - m);
#pragma unroll
    for (int o = 16; o; o >>= 1) ssum += __shfl_xor_sync(0xffffffffu, ssum, o);
    float inv = 1.0f / ssum;
    constexpr int NR = D / 128;
    float4 acc[NR];
#pragma unroll
    for (int r = 0; r < NR; ++r) acc[r] = make_float4(0.f, 0.f, 0.f, 0.f);
    for (int j = p0; j < p1; ++j) {
        int src = g_src[j];
        float alpha = __expf(g_e[g_eid[j]] - m) * inv;
        const float4* row = (const float4*)(xl + (size_t)src * stride);
#pragma unroll
        for (int r = 0; r < NR; ++r) {
            float4 v = row[lane + 32 * r];
            acc[r].x = fmaf(alpha, v.x, acc[r].x);
            acc[r].y = fmaf(alpha, v.y, acc[r].y);
            acc[r].z = fmaf(alpha, v.z, acc[r].z);
            acc[r].w = fmaf(alpha, v.w, acc[r].w);
        }
    }
#pragma unroll
    for (int r = 0; r < NR; ++r) {
        int col = 4 * (lane + 32 * r);
        float4 b = *(const float4*)&bias[col];
        float4 o;
        o.x = acc[r].x + b.x; o.y = acc[r].y + b.y;
        o.z = acc[r].z + b.z; o.w = acc[r].w + b.w;
        if (RELU) {
            o.x = fmaxf(o.x, 0.f); o.y = fmaxf(o.y, 0.f);
            o.z = fmaxf(o.z, 0.f); o.w = fmaxf(o.w, 0.f);
        }
        *(float4*)&out[(size_t)node * D + col] = o;
    }
}

// heads: hcat row layout (stride S): [xl_mu(16)|xr_mu(16)|xl_ls(16)|xr_ls(16)|pad]
__global__ void edge_score_heads_kernel(const int* __restrict__ ei, const float* __restrict__ hcat,
                                        int S,
                                        const float* __restrict__ att_mu, const float* __restrict__ att_ls) {
    int i = blockIdx.x * blockDim.x + threadIdx.x;
    if (i >= ETOT) return;
    int s, d; edge_decode(ei, i, s, d);
    const float4* Sp = (const float4*)(hcat + (size_t)s * S);
    const float4* Dp = (const float4*)(hcat + (size_t)d * S);
    const float4* Am = (const float4*)att_mu;
    const float4* Al = (const float4*)att_ls;
    float emu = 0.f, els = 0.f;
#pragma unroll
    for (int q = 0; q < 4; ++q) {
        float4 l = Sp[q], r = Dp[4 + q], a = Am[q];
        float v;
        v = l.x + r.x; v = (v > 0.f) ? v : 0.2f * v; emu = fmaf(v, a.x, emu);
        v = l.y + r.y; v = (v > 0.f) ? v : 0.2f * v; emu = fmaf(v, a.y, emu);
        v = l.z + r.z; v = (v > 0.f) ? v : 0.2f * v; emu = fmaf(v, a.z, emu);
        v = l.w + r.w; v = (v > 0.f) ? v : 0.2f * v; emu = fmaf(v, a.w, emu);
        float4 l2 = Sp[8 + q], r2 = Dp[12 + q], a2 = Al[q];
        v = l2.x + r2.x; v = (v > 0.f) ? v : 0.2f * v; els = fmaf(v, a2.x, els);
        v = l2.y + r2.y; v = (v > 0.f) ? v : 0.2f * v; els = fmaf(v, a2.y, els);
        v = l2.z + r2.z; v = (v > 0.f) ? v : 0.2f * v; els = fmaf(v, a2.z, els);
        v = l2.w + r2.w; v = (v > 0.f) ? v : 0.2f * v; els = fmaf(v, a2.w, els);
    }
    g_e[i] = emu;
    g_e2[i] = els;
}

__global__ void node_agg_heads_kernel(const float* __restrict__ hcat, int S,
                                      const float* __restrict__ bmu, const float* __restrict__ bls,
                                      float* __restrict__ omu, float* __restrict__ ols) {
    int node = (blockIdx.x * blockDim.x + threadIdx.x) >> 5;
    int lane = threadIdx.x & 31;
    if (node >= NNODES) return;
    int p0 = g_ptr[node], p1 = g_ptr[node + 1];
    float mmu = NEG_INF, mls = NEG_INF;
    for (int j = p0 + lane; j < p1; j += 32) {
        int e = g_eid[j];
        mmu = fmaxf(mmu, g_e[e]);
        mls = fmaxf(mls, g_e2[e]);
    }
#pragma unroll
    for (int o = 16; o; o >>= 1) {
        mmu = fmaxf(mmu, __shfl_xor_sync(0xffffffffu, mmu, o));
        mls = fmaxf(mls, __shfl_xor_sync(0xffffffffu, mls, o));
    }
    float smu = 0.f, sls = 0.f;
    for (int j = p0 + lane; j < p1; j += 32) {
        int e = g_eid[j];
        smu += __expf(g_e[e] - mmu);
        sls += __expf(g_e2[e] - mls);
    }
#pragma unroll
    for (int o = 16; o; o >>= 1) {
        smu += __shfl_xor_sync(0xffffffffu, smu, o);
        sls += __shfl_xor_sync(0xffffffffu, sls, o);
    }
    float imu = 1.0f / smu, ils = 1.0f / sls;
    float acc = 0.0f;
    for (int j = p0; j < p1; ++j) {
        int s = g_src[j], e = g_eid[j];
        const float* row = hcat + (size_t)s * S;
        if (lane < 16) acc = fmaf(__expf(g_e[e]  - mmu) * imu, row[lane],      acc);
        else           acc = fmaf(__expf(g_e2[e] - mls) * ils, row[16 + lane], acc);
    }
    if (lane < 16) omu[(size_t)node * 16 + lane]        = acc + bmu[lane];
    else           ols[(size_t)node * 16 + (lane - 16)] = acc + bls[lane - 16];
}

__global__ void z_kernel(const float* __restrict__ eps, const float* __restrict__ ls,
                         const float* __restrict__ mu, float* __restrict__ z, int total) {
    int i = blockIdx.x * blockDim.x + threadIdx.x;
    if (i < total) z[i] = eps[i] * expf(ls[i]) + mu[i];
}

// adj = sigmoid(z @ z^T), z [NNODES,16].  64x64 tile, 256 thr, 4x4 per thread.
__global__ void adj_kernel(const float* __restrict__ z, float* __restrict__ out) {
    __shared__ float zr[64][17];
    __shared__ float zc[64][17];
    const int t = threadIdx.x, br = blockIdx.y * 64, bc = blockIdx.x * 64;
    {
        int row = t >> 2, seg = (t & 3) * 4;
        float4 v = *(const float4*)(z + (size_t)(br + row) * 16 + seg);
        zr[row][seg + 0] = v.x; zr[row][seg + 1] = v.y; zr[row][seg + 2] = v.z; zr[row][seg + 3] = v.w;
        float4 w = *(const float4*)(z + (size_t)(bc + row) * 16 + seg);
        zc[row][seg + 0] = w.x; zc[row][seg + 1] = w.y; zc[row][seg + 2] = w.z; zc[row][seg + 3] = w.w;
    }
    __syncthreads();
    const int tr = (t / 16) * 4, tc = (t % 16) * 4;
    float acc[4][4] = {{0.f}};
#pragma unroll
    for (int k = 0; k < 16; ++k) {
        float a[4], b[4];
#pragma unroll
        for (int i = 0; i < 4; ++i) a[i] = zr[tr + i][k];
#pragma unroll
        for (int j = 0; j < 4; ++j) b[j] = zc[tc + j][k];
#pragma unroll
        for (int i = 0; i < 4; ++i)
#pragma unroll
            for (int j = 0; j < 4; ++j) acc[i][j] = fmaf(a[i], b[j], acc[i][j]);
    }
#pragma unroll
    for (int i = 0; i < 4; ++i) {
        float4 o;
        o.x = fast_sigmoid(acc[i][0]); o.y = fast_sigmoid(acc[i][1]);
        o.z = fast_sigmoid(acc[i][2]); o.w = fast_sigmoid(acc[i][3]);
        *(float4*)(out + (size_t)(br + tr + i) * NNODES + bc + tc) = o;
    }
}

// ---------------- BatchNorm ----------------
__global__ void bn_zero_kernel(int F) {
    int i = blockIdx.x * blockDim.x + threadIdx.x;
    if (i < F) { g_sum[i] = 0.0; g_sumsq[i] = 0.0; }
}
__global__ void bn_stats_kernel(const float* __restrict__ x, int rows, int F) {
    int chunk = (rows + gridDim.x - 1) / gridDim.x;
    int r0 = blockIdx.x * chunk, r1 = min(rows, r0 + chunk), t = threadIdx.x;
    if (F <= 256) {
        int per = 256 / F, f = t % F, roff = t / F;
        double s = 0.0, q = 0.0;
        for (int r = r0 + roff; r < r1; r += per) {
            float v = x[(size_t)r * F + f];
            s += v; q += (double)v * v;
        }
        atomicAdd(&g_sum[f], s); atomicAdd(&g_sumsq[f], q);
    } else {
        for (int f = t; f < F; f += 256) {
            double s = 0.0, q = 0.0;
            for (int r = r0; r < r1; ++r) {
                float v = x[(size_t)r * F + f];
                s += v; q += (double)v * v;
            }
            atomicAdd(&g_sum[f], s); atomicAdd(&g_sumsq[f], q);
        }
    }
}
__global__ void bn_finalize_kernel(const float* __restrict__ g, const float* __restrict__ b,
                                   int F, int rows) {
    int f = blockIdx.x * blockDim.x + threadIdx.x;
    if (f >= F) return;
    double mean = g_sum[f] / (double)rows;
    double var  = g_sumsq[f] / (double)rows - mean * mean;
    double inv  = rsqrt(var + 1e-5);
    float sc = (float)((double)g[f] * inv);
    g_scale[f] = sc;
    g_shift[f] = b[f] - (float)mean * sc;
}
__global__ void bn_apply_kernel(float* __restrict__ x, int total, int F) {
    int i = blockIdx.x * blockDim.x + threadIdx.x;
    if (i >= total) return;
    int f = i % F;
    float v = x[i] * g_scale[f] + g_shift[f];
    x[i] = (v > 0.0f) ? v : 0.2f * v;
}

// ---------------- Host helpers ----------------
static void conv_A(const float* A, int K, int Kp, __nv_bfloat16* hi, __nv_bfloat16* lo) {
    size_t total = (size_t)NNODES * Kp;
    convA_kernel<<<(unsigned)((total + 255) / 256), 256>>>(A, K, Kp, hi, lo);
}
static void wmma_gemm(const __nv_bfloat16* ahi, const __nv_bfloat16* alo, int Kp,
                      const __nv_bfloat16* whi, const __nv_bfloat16* wlo,
                      const float* bias, float* C, int Np, int ldc, int Nact, int epi) {
    dim3 grid(Np / 128, NNODES / 128);
    if (epi == 0)
        wmma_gemm_kernel<0><<<grid, 256, TCSM_BYTES>>>(ahi, alo, Kp, whi, wlo, bias, C, ldc, Nact);
    else
        wmma_gemm_kernel<2><<<grid, 256, TCSM_BYTES>>>(ahi, alo, Kp, whi, wlo, bias, C, ldc, Nact);
}
static void run_bn(float* x, const float* g, const float* b, int rows, int F) {
    bn_zero_kernel<<<(F + 255) / 256, 256>>>(F);
    bn_stats_kernel<<<64, 256>>>(x, rows, F);
    bn_finalize_kernel<<<(F + 255) / 256, 256>>>(g, b, F, rows);
    bn_apply_kernel<<<(rows * F + 255) / 256, 256>>>(x, rows * F, F);
}

// ---------------- kernel_launch ----------------
extern "C" void kernel_launch(void* const* d_in, const int* in_sizes, int n_in,
                              void* d_out, int out_size) {
    (void)in_sizes; (void)n_in; (void)out_size;

    const float* x       = (const float*)d_in[0];
    const int*   ei      = (const int*)  d_in[1];
    const float* eps     = (const float*)d_in[2];
    const float* c1_Wl   = (const float*)d_in[3];
    const float* c1_Wr   = (const float*)d_in[4];
    const float* c1_att  = (const float*)d_in[5];
    const float* c1_b    = (const float*)d_in[6];
    const float* c2_Wl   = (const float*)d_in[7];
    const float* c2_Wr   = (const float*)d_in[8];
    const float* c2_att  = (const float*)d_in[9];
    const float* c2_b    = (const float*)d_in[10];
    const float* cmu_Wl  = (const float*)d_in[11];
    const float* cmu_Wr  = (const float*)d_in[12];
    const float* cmu_att = (const float*)d_in[13];
    const float* cmu_b   = (const float*)d_in[14];
    const float* cls_Wl  = (const float*)d_in[15];
    const float* cls_Wr  = (const float*)d_in[16];
    const float* cls_att = (const float*)d_in[17];
    const float* cls_b   = (const float*)d_in[18];
    const float* d1_W    = (const float*)d_in[19];
    const float* bn1_g   = (const float*)d_in[21];
    const float* bn1_b   = (const float*)d_in[22];
    const float* d2_W    = (const float*)d_in[23];
    const float* bn2_g   = (const float*)d_in[25];
    const float* bn2_b   = (const float*)d_in[26];
    const float* d3_W    = (const float*)d_in[27];
    const float* d3_b    = (const float*)d_in[28];

    float* out   = (float*)d_out;
    float* d_z   = out + Z_OFF;
    float* d_y   = out + Y_OFF;
    float* d_mu  = out + MU_OFF;
    float* d_ls  = out + LS_OFF;
    float* d_adj = out + ADJ_OFF;

    cudaFuncSetAttribute(wmma_gemm_kernel<0>, cudaFuncAttributeMaxDynamicSharedMemorySize, TCSM_BYTES);
    cudaFuncSetAttribute(wmma_gemm_kernel<2>, cudaFuncAttributeMaxDynamicSharedMemorySize, TCSM_BYTES);

    float *xlr, *h, *cs;
    __nv_bfloat16 *ahi, *alo, *whi, *wlo;
    cudaGetSymbolAddress((void**)&xlr, g_xlr);
    cudaGetSymbolAddress((void**)&h,   g_h);
    cudaGetSymbolAddress((void**)&cs,  g_cs);
    cudaGetSymbolAddress((void**)&ahi, g_ahi);
    cudaGetSymbolAddress((void**)&alo, g_alo);
    cudaGetSymbolAddress((void**)&whi, g_whi);
    cudaGetSymbolAddress((void**)&wlo, g_wlo);

    const int EB = (ETOT + 255) / 256;
    const int EW = ETOT / 8;
    const int NW = NNODES / 8;

    cnt_zero_kernel<<<(NNODES + 255) / 256, 256>>>();
    hist_kernel<<<EB, 256>>>(ei);
    scan_kernel<<<1, 1024>>>();
    scatter_kernel<<<EB, 256>>>(ei);

    // GAT layer 1: 3000 -> 256 (fused Wl|Wr, Np=512, Kp=3008)
    zeroW_kernel<<<(512 * 3008 + 255) / 256, 256>>>(whi, wlo, 512 * 3008);
    convW_kernel<<<(DIN * 256 + 255) / 256, 256>>>(c1_Wl, DIN, 256, 3008, 0,   whi, wlo);
    convW_kernel<<<(DIN * 256 + 255) / 256, 256>>>(c1_Wr, DIN, 256, 3008, 256, whi, wlo);
    conv_A(x, DIN, 3008, ahi, alo);
    wmma_gemm(ahi, alo, 3008, whi, wlo, nullptr, xlr, 512, 512, 512, 0);
    edge_score_kernel<<<EW, 256>>>(ei, xlr, xlr + DH1, c1_att, DH1, 512);
    node_agg_kernel<DH1, 1><<<NW, 256>>>(xlr, 512, c1_b, h);

    // GAT layer 2: 256 -> 128 (Np=256)
    zeroW_kernel<<<(256 * 256 + 255) / 256, 256>>>(whi, wlo, 256 * 256);
    convW_kernel<<<(256 * 128 + 255) / 256, 256>>>(c2_Wl, 256, 128, 256, 0,   whi, wlo);
    convW_kernel<<<(256 * 128 + 255) / 256, 256>>>(c2_Wr, 256, 128, 256, 128, whi, wlo);
    conv_A(h, 256, 256, ahi, alo);
    wmma_gemm(ahi, alo, 256, whi, wlo, nullptr, xlr, 256, 256, 256, 0);
    edge_score_kernel<<<EW, 256>>>(ei, xlr, xlr + DH2, c2_att, DH2, 256);
    node_agg_kernel<DH2, 1><<<NW, 256>>>(xlr, 256, c2_b, h);

    // mu/logstd heads: 128 -> 4x16 (Np=128) -> cs stride 128
    zeroW_kernel<<<(128 * 128 + 255) / 256, 256>>>(whi, wlo, 128 * 128);
    convW_kernel<<<(128 * 16 + 255) / 256, 256>>>(cmu_Wl, 128, 16, 128, 0,  whi, wlo);
    convW_kernel<<<(128 * 16 + 255) / 256, 256>>>(cmu_Wr, 128, 16, 128, 16, whi, wlo);
    convW_kernel<<<(128 * 16 + 255) / 256, 256>>>(cls_Wl, 128, 16, 128, 32, whi, wlo);
    convW_kernel<<<(128 * 16 + 255) / 256, 256>>>(cls_Wr, 128, 16, 128, 48, whi, wlo);
    conv_A(h, 128, 128, ahi, alo);
    wmma_gemm(ahi, alo, 128, whi, wlo, nullptr, cs, 128, 128, 128, 0);
    edge_score_heads_kernel<<<EB, 256>>>(ei, cs, 128, cmu_att, cls_att);
    node_agg_heads_kernel<<<NW, 256>>>(cs, 128, cmu_b, cls_b, d_mu, d_ls);

    // z, adj (scalar tile kernel — near store-bound floor)
    z_kernel<<<(Z_LEN + 255) / 256, 256>>>(eps, d_ls, d_mu, d_z, Z_LEN);
    {
        dim3 grid(NNODES / 64, NNODES / 64);
        adj_kernel<<<grid, 256>>>(d_z, d_adj);
    }

    // d1: 16 -> 128 (bias cancels in train-mode BN), Kp=32 -> g_h
    zeroW_kernel<<<(128 * 32 + 255) / 256, 256>>>(whi, wlo, 128 * 32);
    convW_kernel<<<(16 * 128 + 255) / 256, 256>>>(d1_W, 16, 128, 32, 0, whi, wlo);
    conv_A(d_z, 16, 32, ahi, alo);
    wmma_gemm(ahi, alo, 32, whi, wlo, nullptr, h, 128, 128, 128, 0);
    run_bn(h, bn1_g, bn1_b, NNODES, 128);

    // d2: 128 -> 512 (bias cancels in BN) -> g_xlr
    zeroW_kernel<<<(512 * 128 + 255) / 256, 256>>>(whi, wlo, 512 * 128);
    convW_kernel<<<(128 * 512 + 255) / 256, 256>>>(d2_W, 128, 512, 128, 0, whi, wlo);
    conv_A(h, 128, 128, ahi, alo);
    wmma_gemm(ahi, alo, 128, whi, wlo, nullptr, xlr, 512, 512, 512, 0);
    run_bn(xlr, bn2_g, bn2_b, NNODES, 512);

    // d3: 512 -> 3000, EPI=2 (bias+sigmoid) direct to d_y (ldc=3000, guarded)
    zeroW_kernel<<<(3072 * 512 + 255) / 256, 256>>>(whi, wlo, 3072 * 512);
    convW_kernel<<<(512 * DOUT + 255) / 256, 256>>>(d3_W, 512, DOUT, 512, 0, whi, wlo);
    conv_A(xlr, 512, 512, ahi, alo);
    wmma_gemm(ahi, alo, 512, whi, wlo, d3_b, d_y, 3072, DOUT, DOUT, 2);
}